// round 3
// baseline (speedup 1.0000x reference)
#include <cuda_runtime.h>
#include <cuda_bf16.h>
#include <cstdint>
#include <cstddef>

#define NN       16384
#define NFEAT    256
#define NH       64
#define SSTAGE   6
#define NCHUNK   512               // 16384 / 32 K-floats per chunk
#define A_PITCHF 36                // 32 floats padded to 36 (144 B) - bank-conflict-free
#define B_PITCHF 36
#define A_STAGE  (128 * 144)       // 18432 B
#define B_STAGE  (64 * 144)        // 9216 B
#define STAGE_B  (A_STAGE + B_STAGE)
#define DYN      (SSTAGE * STAGE_B)   // 165888 B dynamic smem

// ---------------- device scratch (no runtime allocation) --------------------
__device__ __align__(16) float  g_XW1T[(size_t)NH * NN];  // (x@W1)^T, tf32-rounded
__device__ __align__(8)  float2 g_T[NN];                  // relu(adj@XW1+b1)@W2
__device__ unsigned g_maxkey[2];

// ---------------- helpers ----------------------------------------------------
__device__ __forceinline__ void cp_async16(void* s, const float* g) {
    uint32_t sa = (uint32_t)__cvta_generic_to_shared(s);
    asm volatile("cp.async.cg.shared.global [%0], [%1], 16;"
                 :: "r"(sa), "l"(__cvta_generic_to_global(g)) : "memory");
}
#define CP_COMMIT() asm volatile("cp.async.commit_group;" ::: "memory")
#define CP_WAIT(n)  asm volatile("cp.async.wait_group %0;" :: "n"(n) : "memory")

__device__ __forceinline__ uint32_t f2tf(float f) {
    uint32_t r;
    asm("cvt.rna.tf32.f32 %0, %1;" : "=r"(r) : "f"(f));
    return r;
}

__device__ __forceinline__ void mma_tf32(float* c, uint32_t a0, uint32_t a1,
                                         uint32_t a2, uint32_t a3,
                                         uint32_t b0, uint32_t b1) {
    asm volatile("mma.sync.aligned.m16n8k8.row.col.f32.tf32.tf32.f32 "
                 "{%0,%1,%2,%3}, {%4,%5,%6,%7}, {%8,%9}, {%0,%1,%2,%3};"
                 : "+f"(c[0]), "+f"(c[1]), "+f"(c[2]), "+f"(c[3])
                 : "r"(a0), "r"(a1), "r"(a2), "r"(a3), "r"(b0), "r"(b1));
}

// float <-> order-preserving uint key (for atomic max pooling)
__device__ __forceinline__ unsigned fkey(float f) {
    unsigned b = __float_as_uint(f);
    return (b & 0x80000000u) ? ~b : (b | 0x80000000u);
}
__device__ __forceinline__ float fdec(unsigned k) {
    unsigned b = (k & 0x80000000u) ? (k ^ 0x80000000u) : ~k;
    return __uint_as_float(b);
}

// ================= kernel 1: XW1^T = (x @ W1)^T, tf32-rounded ===============
__global__ void __launch_bounds__(256) k_xw1t(const float* __restrict__ x,
                                              const float* __restrict__ W1) {
    __shared__ float sx[32 * 257];
    const int tid = threadIdx.x;
    const int nodes0 = blockIdx.x * 32;

    if (blockIdx.x == 0 && tid < 2) g_maxkey[tid] = 0u;   // reset pooling keys

    for (int i = tid; i < 32 * 64; i += 256) {
        int r = i >> 6, c4 = i & 63;
        float4 v = *(const float4*)(x + (size_t)(nodes0 + r) * NFEAT + c4 * 4);
        float* d = &sx[r * 257 + c4 * 4];
        d[0] = v.x; d[1] = v.y; d[2] = v.z; d[3] = v.w;
    }
    __syncthreads();

    const int hb = (tid & 15) * 4;
    const int n0 = (tid >> 4) * 2;
    float a0x = 0, a0y = 0, a0z = 0, a0w = 0;
    float a1x = 0, a1y = 0, a1z = 0, a1w = 0;
    #pragma unroll 4
    for (int m = 0; m < NFEAT; m++) {
        float4 w = __ldg((const float4*)(W1 + m * NH + hb));
        float x0 = sx[n0 * 257 + m];
        float x1 = sx[(n0 + 1) * 257 + m];
        a0x = fmaf(x0, w.x, a0x); a0y = fmaf(x0, w.y, a0y);
        a0z = fmaf(x0, w.z, a0z); a0w = fmaf(x0, w.w, a0w);
        a1x = fmaf(x1, w.x, a1x); a1y = fmaf(x1, w.y, a1y);
        a1z = fmaf(x1, w.z, a1z); a1w = fmaf(x1, w.w, a1w);
    }
    size_t nd = (size_t)nodes0 + n0;
    g_XW1T[(size_t)(hb+0)*NN + nd]   = __uint_as_float(f2tf(a0x));
    g_XW1T[(size_t)(hb+0)*NN + nd+1] = __uint_as_float(f2tf(a1x));
    g_XW1T[(size_t)(hb+1)*NN + nd]   = __uint_as_float(f2tf(a0y));
    g_XW1T[(size_t)(hb+1)*NN + nd+1] = __uint_as_float(f2tf(a1y));
    g_XW1T[(size_t)(hb+2)*NN + nd]   = __uint_as_float(f2tf(a0z));
    g_XW1T[(size_t)(hb+2)*NN + nd+1] = __uint_as_float(f2tf(a1z));
    g_XW1T[(size_t)(hb+3)*NN + nd]   = __uint_as_float(f2tf(a0w));
    g_XW1T[(size_t)(hb+3)*NN + nd+1] = __uint_as_float(f2tf(a1w));
}

// ================= kernel 2: T = relu(adj @ XW1 + b1) @ W2  (HMMA tf32) =====
__device__ __forceinline__ void p1_load(const float* __restrict__ adj, size_t row0,
                                        int c, int tid, char* smem) {
    char* st = smem + (c % SSTAGE) * STAGE_B;
    const float* gA = adj + row0 * NN + (size_t)c * 32;
    const float* gB = g_XW1T + (size_t)c * 32;
    #pragma unroll
    for (int i = 0; i < 8; i++) {                  // A: 128 rows x 8 x 16B
        int seg = tid + i * 128;
        int r = seg >> 3, c8 = seg & 7;
        cp_async16(st + r * 144 + c8 * 16, gA + (size_t)r * NN + c8 * 4);
    }
    #pragma unroll
    for (int i = 0; i < 4; i++) {                  // B: 64 rows x 8 x 16B
        int seg = tid + i * 128;
        int r = seg >> 3, c8 = seg & 7;
        cp_async16(st + A_STAGE + r * 144 + c8 * 16, gB + (size_t)r * NN + c8 * 4);
    }
}

__global__ void __launch_bounds__(128, 1)
k_pass1(const float* __restrict__ adj, const float* __restrict__ b1,
        const float* __restrict__ W2) {
    extern __shared__ __align__(16) char smem[];
    const int tid  = threadIdx.x;
    const int warp = tid >> 5, lane = tid & 31;
    const int g = lane >> 2, tig = lane & 3;
    const size_t row0 = (size_t)blockIdx.x * 128;

    float acc[2][8][4];
    #pragma unroll
    for (int mt = 0; mt < 2; mt++)
        #pragma unroll
        for (int nt = 0; nt < 8; nt++)
            #pragma unroll
            for (int q = 0; q < 4; q++) acc[mt][nt][q] = 0.f;

    for (int s = 0; s < SSTAGE - 1; s++) { p1_load(adj, row0, s, tid, smem); CP_COMMIT(); }

    for (int c = 0; c < NCHUNK; c++) {
        CP_WAIT(SSTAGE - 2);
        __syncthreads();
        if (c + SSTAGE - 1 < NCHUNK) p1_load(adj, row0, c + SSTAGE - 1, tid, smem);
        CP_COMMIT();

        const float* SA = (const float*)(smem + (c % SSTAGE) * STAGE_B);
        const float* SB = (const float*)(smem + (c % SSTAGE) * STAGE_B + A_STAGE);
        #pragma unroll
        for (int ks = 0; ks < 4; ks++) {
            uint32_t bf[8][2];
            #pragma unroll
            for (int nt = 0; nt < 8; nt++) {
                const float* br = SB + (nt * 8 + g) * B_PITCHF + ks * 8 + tig;
                bf[nt][0] = __float_as_uint(br[0]);
                bf[nt][1] = __float_as_uint(br[4]);
            }
            #pragma unroll
            for (int mt = 0; mt < 2; mt++) {
                const float* ar = SA + (warp * 32 + mt * 16 + g) * A_PITCHF + ks * 8 + tig;
                uint32_t a0 = f2tf(ar[0]);
                uint32_t a1 = f2tf(ar[8 * A_PITCHF]);
                uint32_t a2 = f2tf(ar[4]);
                uint32_t a3 = f2tf(ar[8 * A_PITCHF + 4]);
                #pragma unroll
                for (int nt = 0; nt < 8; nt++)
                    mma_tf32(acc[mt][nt], a0, a1, a2, a3, bf[nt][0], bf[nt][1]);
            }
        }
    }

    // epilogue: relu(+b1) @ W2, quad reduce, write T
    float bb[8][2], w20[8][2], w21[8][2];
    #pragma unroll
    for (int nt = 0; nt < 8; nt++) {
        int j0 = nt * 8 + 2 * tig, j1 = j0 + 1;
        bb[nt][0]  = __ldg(b1 + j0);      bb[nt][1]  = __ldg(b1 + j1);
        w20[nt][0] = __ldg(W2 + 2 * j0);  w20[nt][1] = __ldg(W2 + 2 * j1);
        w21[nt][0] = __ldg(W2 + 2 * j0 + 1); w21[nt][1] = __ldg(W2 + 2 * j1 + 1);
    }
    #pragma unroll
    for (int mt = 0; mt < 2; mt++) {
        #pragma unroll
        for (int half = 0; half < 2; half++) {
            float t0 = 0.f, t1 = 0.f;
            #pragma unroll
            for (int nt = 0; nt < 8; nt++) {
                float h0 = fmaxf(acc[mt][nt][half * 2 + 0] + bb[nt][0], 0.f);
                float h1 = fmaxf(acc[mt][nt][half * 2 + 1] + bb[nt][1], 0.f);
                t0 = fmaf(h0, w20[nt][0], fmaf(h1, w20[nt][1], t0));
                t1 = fmaf(h0, w21[nt][0], fmaf(h1, w21[nt][1], t1));
            }
            t0 += __shfl_xor_sync(~0u, t0, 1); t1 += __shfl_xor_sync(~0u, t1, 1);
            t0 += __shfl_xor_sync(~0u, t0, 2); t1 += __shfl_xor_sync(~0u, t1, 2);
            if (tig == 0)
                g_T[row0 + warp * 32 + mt * 16 + half * 8 + g] = make_float2(t0, t1);
        }
    }
}

// ================= kernel 3: adj @ T + b2, fused column max =================
__global__ void __launch_bounds__(256) k_pass2(const float* __restrict__ adj,
                                               const float* __restrict__ b2) {
    __shared__ float sT0[4096];
    __shared__ float sT1[4096];
    __shared__ unsigned smax[8][2];
    const int tid = threadIdx.x, warp = tid >> 5, lane = tid & 31;
    const size_t row0 = (size_t)blockIdx.x * 32 + warp * 4;

    float a00 = 0, a01 = 0, a10 = 0, a11 = 0, a20 = 0, a21 = 0, a30 = 0, a31 = 0;

    for (int part = 0; part < 4; part++) {
        __syncthreads();
        for (int i = tid; i < 4096; i += 256) {
            float2 t = g_T[part * 4096 + i];
            sT0[i] = t.x; sT1[i] = t.y;
        }
        __syncthreads();
        const float* ap = adj + (size_t)part * 4096;
        #pragma unroll 2
        for (int j = lane * 4; j < 4096; j += 128) {
            float4 t0 = *(const float4*)&sT0[j];
            float4 t1 = *(const float4*)&sT1[j];
            float4 r0 = __ldcs((const float4*)(ap + (row0 + 0) * NN + j));
            float4 r1 = __ldcs((const float4*)(ap + (row0 + 1) * NN + j));
            float4 r2 = __ldcs((const float4*)(ap + (row0 + 2) * NN + j));
            float4 r3 = __ldcs((const float4*)(ap + (row0 + 3) * NN + j));
            a00 = fmaf(r0.x, t0.x, fmaf(r0.y, t0.y, fmaf(r0.z, t0.z, fmaf(r0.w, t0.w, a00))));
            a01 = fmaf(r0.x, t1.x, fmaf(r0.y, t1.y, fmaf(r0.z, t1.z, fmaf(r0.w, t1.w, a01))));
            a10 = fmaf(r1.x, t0.x, fmaf(r1.y, t0.y, fmaf(r1.z, t0.z, fmaf(r1.w, t0.w, a10))));
            a11 = fmaf(r1.x, t1.x, fmaf(r1.y, t1.y, fmaf(r1.z, t1.z, fmaf(r1.w, t1.w, a11))));
            a20 = fmaf(r2.x, t0.x, fmaf(r2.y, t0.y, fmaf(r2.z, t0.z, fmaf(r2.w, t0.w, a20))));
            a21 = fmaf(r2.x, t1.x, fmaf(r2.y, t1.y, fmaf(r2.z, t1.z, fmaf(r2.w, t1.w, a21))));
            a30 = fmaf(r3.x, t0.x, fmaf(r3.y, t0.y, fmaf(r3.z, t0.z, fmaf(r3.w, t0.w, a30))));
            a31 = fmaf(r3.x, t1.x, fmaf(r3.y, t1.y, fmaf(r3.z, t1.z, fmaf(r3.w, t1.w, a31))));
        }
    }
    #pragma unroll
    for (int off = 16; off; off >>= 1) {
        a00 += __shfl_xor_sync(~0u, a00, off); a01 += __shfl_xor_sync(~0u, a01, off);
        a10 += __shfl_xor_sync(~0u, a10, off); a11 += __shfl_xor_sync(~0u, a11, off);
        a20 += __shfl_xor_sync(~0u, a20, off); a21 += __shfl_xor_sync(~0u, a21, off);
        a30 += __shfl_xor_sync(~0u, a30, off); a31 += __shfl_xor_sync(~0u, a31, off);
    }
    if (lane == 0) {
        float bb0 = __ldg(b2), bb1 = __ldg(b2 + 1);
        unsigned k0 = fkey(a00 + bb0), k1 = fkey(a01 + bb1);
        k0 = max(k0, fkey(a10 + bb0)); k1 = max(k1, fkey(a11 + bb1));
        k0 = max(k0, fkey(a20 + bb0)); k1 = max(k1, fkey(a21 + bb1));
        k0 = max(k0, fkey(a30 + bb0)); k1 = max(k1, fkey(a31 + bb1));
        smax[warp][0] = k0; smax[warp][1] = k1;
    }
    __syncthreads();
    if (tid == 0) {
        unsigned k0 = smax[0][0], k1 = smax[0][1];
        #pragma unroll
        for (int w = 1; w < 8; w++) { k0 = max(k0, smax[w][0]); k1 = max(k1, smax[w][1]); }
        atomicMax(&g_maxkey[0], k0);
        atomicMax(&g_maxkey[1], k1);
    }
}

// ================= kernel 4: final linear 2 -> 1 ============================
__global__ void k_final(const float* __restrict__ W3, const float* __restrict__ b3,
                        float* __restrict__ out) {
    float m0 = fdec(g_maxkey[0]);
    float m1 = fdec(g_maxkey[1]);
    out[0] = fmaf(m0, W3[0], fmaf(m1, W3[1], b3[0]));
}

// ================= launch ===================================================
extern "C" void kernel_launch(void* const* d_in, const int* in_sizes, int n_in,
                              void* d_out, int out_size) {
    (void)in_sizes; (void)n_in; (void)out_size;
    const float* x   = (const float*)d_in[0];
    const float* adj = (const float*)d_in[1];
    const float* W1  = (const float*)d_in[2];
    const float* b1  = (const float*)d_in[3];
    const float* W2  = (const float*)d_in[4];
    const float* b2  = (const float*)d_in[5];
    const float* W3  = (const float*)d_in[6];
    const float* b3  = (const float*)d_in[7];
    float* out = (float*)d_out;

    static int cfg_done = 0;
    if (!cfg_done) {
        cudaFuncSetAttribute(k_pass1, cudaFuncAttributeMaxDynamicSharedMemorySize, DYN);
        cfg_done = 1;
    }

    k_xw1t <<<512, 256>>>(x, W1);
    k_pass1<<<128, 128, DYN>>>(adj, b1, W2);
    k_pass2<<<512, 256>>>(adj, b2);
    k_final<<<1, 1>>>(W3, b3, out);
}

// round 4
// speedup vs baseline: 1.3703x; 1.3703x over previous
#include <cuda_runtime.h>
#include <cuda_bf16.h>
#include <cstdint>
#include <cstddef>

#define NN       16384
#define NFEAT    256
#define NH       64
#define SSTAGE   6
#define NCHUNK   512               // 16384 / 32 K-floats per chunk
#define PITCHF   36                // 32 floats padded to 36 (144 B) - conflict-free
#define A_STAGE  (128 * 144)       // 18432 B
#define B_STAGE  (64 * 144)        // 9216 B
#define STAGE_B  (A_STAGE + B_STAGE)
#define DYN      (SSTAGE * STAGE_B)   // 165888 B dynamic smem

// ---------------- device scratch (no runtime allocation) --------------------
__device__ __align__(16) float  g_XW1T[(size_t)NH * NN];  // (x@W1)^T, tf32-rounded
__device__ __align__(8)  float2 g_T[NN];                  // relu(adj@XW1+b1)@W2
__device__ unsigned g_maxkey[2];
__device__ int g_cnt;                                     // zero-init; self-resetting

// ---------------- helpers ----------------------------------------------------
__device__ __forceinline__ void cp_async16(void* s, const float* g) {
    uint32_t sa = (uint32_t)__cvta_generic_to_shared(s);
    asm volatile("cp.async.cg.shared.global [%0], [%1], 16;"
                 :: "r"(sa), "l"(__cvta_generic_to_global(g)) : "memory");
}
#define CP_COMMIT() asm volatile("cp.async.commit_group;" ::: "memory")
#define CP_WAIT(n)  asm volatile("cp.async.wait_group %0;" :: "n"(n) : "memory")

__device__ __forceinline__ uint32_t f2tf(float f) {
    uint32_t r;
    asm("cvt.rna.tf32.f32 %0, %1;" : "=r"(r) : "f"(f));
    return r;
}

__device__ __forceinline__ void mma_tf32(float* c, uint32_t a0, uint32_t a1,
                                         uint32_t a2, uint32_t a3,
                                         uint32_t b0, uint32_t b1) {
    asm volatile("mma.sync.aligned.m16n8k8.row.col.f32.tf32.tf32.f32 "
                 "{%0,%1,%2,%3}, {%4,%5,%6,%7}, {%8,%9}, {%0,%1,%2,%3};"
                 : "+f"(c[0]), "+f"(c[1]), "+f"(c[2]), "+f"(c[3])
                 : "r"(a0), "r"(a1), "r"(a2), "r"(a3), "r"(b0), "r"(b1));
}

// float <-> order-preserving uint key (for atomic max pooling)
__device__ __forceinline__ unsigned fkey(float f) {
    unsigned b = __float_as_uint(f);
    return (b & 0x80000000u) ? ~b : (b | 0x80000000u);
}
__device__ __forceinline__ float fdec(unsigned k) {
    unsigned b = (k & 0x80000000u) ? (k ^ 0x80000000u) : ~k;
    return __uint_as_float(b);
}

// ================= kernel 1: XW1^T = (x @ W1)^T, tf32-rounded ===============
__global__ void __launch_bounds__(256) k_xw1t(const float* __restrict__ x,
                                              const float* __restrict__ W1) {
    __shared__ float sx[32 * 257];
    const int tid = threadIdx.x;
    const int nodes0 = blockIdx.x * 32;

    if (blockIdx.x == 0 && tid < 2) g_maxkey[tid] = 0u;   // reset pooling keys

    for (int i = tid; i < 32 * 64; i += 256) {
        int r = i >> 6, c4 = i & 63;
        float4 v = *(const float4*)(x + (size_t)(nodes0 + r) * NFEAT + c4 * 4);
        float* d = &sx[r * 257 + c4 * 4];
        d[0] = v.x; d[1] = v.y; d[2] = v.z; d[3] = v.w;
    }
    __syncthreads();

    const int hb = (tid & 15) * 4;
    const int n0 = (tid >> 4) * 2;
    float a0x = 0, a0y = 0, a0z = 0, a0w = 0;
    float a1x = 0, a1y = 0, a1z = 0, a1w = 0;
    #pragma unroll 4
    for (int m = 0; m < NFEAT; m++) {
        float4 w = __ldg((const float4*)(W1 + m * NH + hb));
        float x0 = sx[n0 * 257 + m];
        float x1 = sx[(n0 + 1) * 257 + m];
        a0x = fmaf(x0, w.x, a0x); a0y = fmaf(x0, w.y, a0y);
        a0z = fmaf(x0, w.z, a0z); a0w = fmaf(x0, w.w, a0w);
        a1x = fmaf(x1, w.x, a1x); a1y = fmaf(x1, w.y, a1y);
        a1z = fmaf(x1, w.z, a1z); a1w = fmaf(x1, w.w, a1w);
    }
    size_t nd = (size_t)nodes0 + n0;
    g_XW1T[(size_t)(hb+0)*NN + nd]   = __uint_as_float(f2tf(a0x));
    g_XW1T[(size_t)(hb+0)*NN + nd+1] = __uint_as_float(f2tf(a1x));
    g_XW1T[(size_t)(hb+1)*NN + nd]   = __uint_as_float(f2tf(a0y));
    g_XW1T[(size_t)(hb+1)*NN + nd+1] = __uint_as_float(f2tf(a1y));
    g_XW1T[(size_t)(hb+2)*NN + nd]   = __uint_as_float(f2tf(a0z));
    g_XW1T[(size_t)(hb+2)*NN + nd+1] = __uint_as_float(f2tf(a1z));
    g_XW1T[(size_t)(hb+3)*NN + nd]   = __uint_as_float(f2tf(a0w));
    g_XW1T[(size_t)(hb+3)*NN + nd+1] = __uint_as_float(f2tf(a1w));
}

// ================= kernel 2: T = relu(adj @ XW1 + b1) @ W2  (HMMA tf32) =====
// 256 threads: warps 0-3 handle rows (warp*32..+31) for K-halves {0,1};
// warps 4-7 handle the SAME rows for K-halves {2,3}. Combined at the end.
__device__ __forceinline__ void p1_load(const float* __restrict__ adj, size_t row0,
                                        int c, int tid, char* smem) {
    char* st = smem + (c % SSTAGE) * STAGE_B;
    const float* gA = adj + row0 * NN + (size_t)c * 32;
    const float* gB = g_XW1T + (size_t)c * 32;
    #pragma unroll
    for (int i = 0; i < 4; i++) {                  // A: 128 rows x 8 x 16B
        int seg = tid + i * 256;
        int r = seg >> 3, c8 = seg & 7;
        cp_async16(st + r * 144 + c8 * 16, gA + (size_t)r * NN + c8 * 4);
    }
    #pragma unroll
    for (int i = 0; i < 2; i++) {                  // B: 64 rows x 8 x 16B
        int seg = tid + i * 256;
        int r = seg >> 3, c8 = seg & 7;
        cp_async16(st + A_STAGE + r * 144 + c8 * 16, gB + (size_t)r * NN + c8 * 4);
    }
}

__global__ void __launch_bounds__(256, 1)
k_pass1(const float* __restrict__ adj, const float* __restrict__ b1,
        const float* __restrict__ W2) {
    extern __shared__ __align__(16) char smem[];
    const int tid  = threadIdx.x;
    const int warp = tid >> 5, lane = tid & 31;
    const int g = lane >> 2, tig = lane & 3;
    const int wm = warp & 3;                 // row-group (0..3) -> rows wm*32..+31
    const int ksbase = (warp >> 2) * 2;      // K-half split: 0 or 2
    const size_t row0 = (size_t)blockIdx.x * 128;

    float acc[2][8][4];
    #pragma unroll
    for (int mt = 0; mt < 2; mt++)
        #pragma unroll
        for (int nt = 0; nt < 8; nt++)
            #pragma unroll
            for (int q = 0; q < 4; q++) acc[mt][nt][q] = 0.f;

    for (int s = 0; s < SSTAGE - 1; s++) { p1_load(adj, row0, s, tid, smem); CP_COMMIT(); }

    for (int c = 0; c < NCHUNK; c++) {
        CP_WAIT(SSTAGE - 2);
        __syncthreads();
        if (c + SSTAGE - 1 < NCHUNK) p1_load(adj, row0, c + SSTAGE - 1, tid, smem);
        CP_COMMIT();

        const float* SA = (const float*)(smem + (c % SSTAGE) * STAGE_B);
        const float* SB = SA + A_STAGE / 4;
        #pragma unroll
        for (int kk = 0; kk < 2; kk++) {
            const int ks = ksbase + kk;
            uint32_t bf[8][2];
            #pragma unroll
            for (int nt = 0; nt < 8; nt++) {
                const float* br = SB + (nt * 8 + g) * PITCHF + ks * 8 + tig;
                bf[nt][0] = __float_as_uint(br[0]);
                bf[nt][1] = __float_as_uint(br[4]);
            }
            #pragma unroll
            for (int mt = 0; mt < 2; mt++) {
                const float* ar = SA + (wm * 32 + mt * 16 + g) * PITCHF + ks * 8 + tig;
                uint32_t a0 = f2tf(ar[0]);
                uint32_t a1 = f2tf(ar[8 * PITCHF]);
                uint32_t a2 = f2tf(ar[4]);
                uint32_t a3 = f2tf(ar[8 * PITCHF + 4]);
                #pragma unroll
                for (int nt = 0; nt < 8; nt++)
                    mma_tf32(acc[mt][nt], a0, a1, a2, a3, bf[nt][0], bf[nt][1]);
            }
        }
    }

    // ---- combine the two K-half partial accumulators via smem ----
    __syncthreads();
    float* xch = (float*)smem;               // reuse pipeline smem (loop done)
    if (warp >= 4) {
        float* dst = xch + ((warp - 4) * 32 + lane) * 68;
        #pragma unroll
        for (int mt = 0; mt < 2; mt++)
            #pragma unroll
            for (int nt = 0; nt < 8; nt++)
                #pragma unroll
                for (int q = 0; q < 4; q++)
                    dst[mt * 32 + nt * 4 + q] = acc[mt][nt][q];
    }
    __syncthreads();
    if (warp < 4) {
        const float* src = xch + (warp * 32 + lane) * 68;
        #pragma unroll
        for (int mt = 0; mt < 2; mt++)
            #pragma unroll
            for (int nt = 0; nt < 8; nt++)
                #pragma unroll
                for (int q = 0; q < 4; q++)
                    acc[mt][nt][q] += src[mt * 32 + nt * 4 + q];

        // epilogue: relu(+b1) @ W2, quad reduce, write T
        float bb[8][2], w20[8][2], w21[8][2];
        #pragma unroll
        for (int nt = 0; nt < 8; nt++) {
            int j0 = nt * 8 + 2 * tig, j1 = j0 + 1;
            bb[nt][0]  = __ldg(b1 + j0);         bb[nt][1]  = __ldg(b1 + j1);
            w20[nt][0] = __ldg(W2 + 2 * j0);     w20[nt][1] = __ldg(W2 + 2 * j1);
            w21[nt][0] = __ldg(W2 + 2 * j0 + 1); w21[nt][1] = __ldg(W2 + 2 * j1 + 1);
        }
        #pragma unroll
        for (int mt = 0; mt < 2; mt++) {
            #pragma unroll
            for (int half = 0; half < 2; half++) {
                float t0 = 0.f, t1 = 0.f;
                #pragma unroll
                for (int nt = 0; nt < 8; nt++) {
                    float h0 = fmaxf(acc[mt][nt][half * 2 + 0] + bb[nt][0], 0.f);
                    float h1 = fmaxf(acc[mt][nt][half * 2 + 1] + bb[nt][1], 0.f);
                    t0 = fmaf(h0, w20[nt][0], fmaf(h1, w20[nt][1], t0));
                    t1 = fmaf(h0, w21[nt][0], fmaf(h1, w21[nt][1], t1));
                }
                t0 += __shfl_xor_sync(~0u, t0, 1); t1 += __shfl_xor_sync(~0u, t1, 1);
                t0 += __shfl_xor_sync(~0u, t0, 2); t1 += __shfl_xor_sync(~0u, t1, 2);
                if (tig == 0)
                    g_T[row0 + warp * 32 + mt * 16 + half * 8 + g] = make_float2(t0, t1);
            }
        }
    }
}

// ========== kernel 3: adj @ T + b2, fused column max + final linear =========
__global__ void __launch_bounds__(256) k_pass2(const float* __restrict__ adj,
                                               const float* __restrict__ b2,
                                               const float* __restrict__ W3,
                                               const float* __restrict__ b3,
                                               float* __restrict__ out) {
    __shared__ float sT0[4096];
    __shared__ float sT1[4096];
    __shared__ unsigned smax[8][2];
    const int tid = threadIdx.x, warp = tid >> 5, lane = tid & 31;
    const size_t row0 = (size_t)blockIdx.x * 32 + warp * 4;

    float a00 = 0, a01 = 0, a10 = 0, a11 = 0, a20 = 0, a21 = 0, a30 = 0, a31 = 0;

    for (int part = 0; part < 4; part++) {
        __syncthreads();
        for (int i = tid; i < 4096; i += 256) {
            float2 t = g_T[part * 4096 + i];
            sT0[i] = t.x; sT1[i] = t.y;
        }
        __syncthreads();
        const float* ap = adj + (size_t)part * 4096;
        #pragma unroll 2
        for (int j = lane * 4; j < 4096; j += 128) {
            float4 t0 = *(const float4*)&sT0[j];
            float4 t1 = *(const float4*)&sT1[j];
            float4 r0 = __ldcs((const float4*)(ap + (row0 + 0) * NN + j));
            float4 r1 = __ldcs((const float4*)(ap + (row0 + 1) * NN + j));
            float4 r2 = __ldcs((const float4*)(ap + (row0 + 2) * NN + j));
            float4 r3 = __ldcs((const float4*)(ap + (row0 + 3) * NN + j));
            a00 = fmaf(r0.x, t0.x, fmaf(r0.y, t0.y, fmaf(r0.z, t0.z, fmaf(r0.w, t0.w, a00))));
            a01 = fmaf(r0.x, t1.x, fmaf(r0.y, t1.y, fmaf(r0.z, t1.z, fmaf(r0.w, t1.w, a01))));
            a10 = fmaf(r1.x, t0.x, fmaf(r1.y, t0.y, fmaf(r1.z, t0.z, fmaf(r1.w, t0.w, a10))));
            a11 = fmaf(r1.x, t1.x, fmaf(r1.y, t1.y, fmaf(r1.z, t1.z, fmaf(r1.w, t1.w, a11))));
            a20 = fmaf(r2.x, t0.x, fmaf(r2.y, t0.y, fmaf(r2.z, t0.z, fmaf(r2.w, t0.w, a20))));
            a21 = fmaf(r2.x, t1.x, fmaf(r2.y, t1.y, fmaf(r2.z, t1.z, fmaf(r2.w, t1.w, a21))));
            a30 = fmaf(r3.x, t0.x, fmaf(r3.y, t0.y, fmaf(r3.z, t0.z, fmaf(r3.w, t0.w, a30))));
            a31 = fmaf(r3.x, t1.x, fmaf(r3.y, t1.y, fmaf(r3.z, t1.z, fmaf(r3.w, t1.w, a31))));
        }
    }
    #pragma unroll
    for (int off = 16; off; off >>= 1) {
        a00 += __shfl_xor_sync(~0u, a00, off); a01 += __shfl_xor_sync(~0u, a01, off);
        a10 += __shfl_xor_sync(~0u, a10, off); a11 += __shfl_xor_sync(~0u, a11, off);
        a20 += __shfl_xor_sync(~0u, a20, off); a21 += __shfl_xor_sync(~0u, a21, off);
        a30 += __shfl_xor_sync(~0u, a30, off); a31 += __shfl_xor_sync(~0u, a31, off);
    }
    if (lane == 0) {
        float bb0 = __ldg(b2), bb1 = __ldg(b2 + 1);
        unsigned k0 = fkey(a00 + bb0), k1 = fkey(a01 + bb1);
        k0 = max(k0, fkey(a10 + bb0)); k1 = max(k1, fkey(a11 + bb1));
        k0 = max(k0, fkey(a20 + bb0)); k1 = max(k1, fkey(a21 + bb1));
        k0 = max(k0, fkey(a30 + bb0)); k1 = max(k1, fkey(a31 + bb1));
        smax[warp][0] = k0; smax[warp][1] = k1;
    }
    __syncthreads();
    if (tid == 0) {
        unsigned k0 = smax[0][0], k1 = smax[0][1];
        #pragma unroll
        for (int w = 1; w < 8; w++) { k0 = max(k0, smax[w][0]); k1 = max(k1, smax[w][1]); }
        atomicMax(&g_maxkey[0], k0);
        atomicMax(&g_maxkey[1], k1);
        __threadfence();
        if (atomicAdd(&g_cnt, 1) == (int)gridDim.x - 1) {     // last CTA finishes
            float m0 = fdec(atomicMax(&g_maxkey[0], 0u));
            float m1 = fdec(atomicMax(&g_maxkey[1], 0u));
            out[0] = fmaf(m0, __ldg(W3), fmaf(m1, __ldg(W3 + 1), __ldg(b3)));
            g_cnt = 0;                                        // reset for next replay
        }
    }
}

// ================= launch ===================================================
extern "C" void kernel_launch(void* const* d_in, const int* in_sizes, int n_in,
                              void* d_out, int out_size) {
    (void)in_sizes; (void)n_in; (void)out_size;
    const float* x   = (const float*)d_in[0];
    const float* adj = (const float*)d_in[1];
    const float* W1  = (const float*)d_in[2];
    const float* b1  = (const float*)d_in[3];
    const float* W2  = (const float*)d_in[4];
    const float* b2  = (const float*)d_in[5];
    const float* W3  = (const float*)d_in[6];
    const float* b3  = (const float*)d_in[7];
    float* out = (float*)d_out;

    static int cfg_done = 0;
    if (!cfg_done) {
        cudaFuncSetAttribute(k_pass1, cudaFuncAttributeMaxDynamicSharedMemorySize, DYN);
        cfg_done = 1;
    }

    k_xw1t <<<512, 256>>>(x, W1);
    k_pass1<<<128, 256, DYN>>>(adj, b1, W2);
    k_pass2<<<512, 256>>>(adj, b2, W3, b3, out);
}

// round 6
// speedup vs baseline: 1.5785x; 1.1519x over previous
#include <cuda_runtime.h>
#include <cuda_bf16.h>
#include <cuda_fp16.h>
#include <cstdint>
#include <cstddef>

#define NN       16384
#define NFEAT    256
#define NH       64
#define SSTAGE   8
#define NCHUNK   512               // 16384 / 32 K-floats per chunk
#define APITCHF  36                // A row: 32 floats padded to 36 (144 B)
#define BPITCHH  40                // B row: 32 halfs padded to 40 (80 B) - conflict-free
#define A_STAGE  (128 * 144)       // 18432 B
#define B_STAGE  (64 * 80)         // 5120 B
#define STAGE_B  (A_STAGE + B_STAGE)
#define DYN      (SSTAGE * STAGE_B)   // 188416 B dynamic smem
#define XW_DYN   (NFEAT * NH * 4 + 64 * 260 * 4)   // W1 + x tile = 132096 B

#define ADJ_SCALE  16384.0f            // 2^14, exact
#define ADJ_ISCALE 6.103515625e-05f    // 2^-14, exact

// ---------------- device scratch (no runtime allocation) --------------------
__device__ __align__(16) __half g_XW1T[(size_t)NH * NN];  // (x@W1)^T in f16
__device__ __align__(8)  float2 g_T[NN];                  // relu(adj@XW1+b1)@W2
__device__ unsigned g_maxkey[2];
__device__ int g_cnt;                                     // zero-init; self-resetting

// ---------------- helpers ----------------------------------------------------
__device__ __forceinline__ void cp_async16(void* s, const void* g) {
    uint32_t sa = (uint32_t)__cvta_generic_to_shared(s);
    asm volatile("cp.async.cg.shared.global [%0], [%1], 16;"
                 :: "r"(sa), "l"(__cvta_generic_to_global(g)) : "memory");
}
#define CP_COMMIT() asm volatile("cp.async.commit_group;" ::: "memory")
#define CP_WAIT(n)  asm volatile("cp.async.wait_group %0;" :: "n"(n) : "memory")

__device__ __forceinline__ void mma_f16(float* c, uint32_t a0, uint32_t a1,
                                        uint32_t a2, uint32_t a3,
                                        uint32_t b0, uint32_t b1) {
    asm volatile("mma.sync.aligned.m16n8k16.row.col.f32.f16.f16.f32 "
                 "{%0,%1,%2,%3}, {%4,%5,%6,%7}, {%8,%9}, {%0,%1,%2,%3};"
                 : "+f"(c[0]), "+f"(c[1]), "+f"(c[2]), "+f"(c[3])
                 : "r"(a0), "r"(a1), "r"(a2), "r"(a3), "r"(b0), "r"(b1));
}

__device__ __forceinline__ uint32_t pack_h2(float lo, float hi) {
    __half2 h = __floats2half2_rn(lo, hi);    // x=lo (low 16b), y=hi
    return *reinterpret_cast<uint32_t*>(&h);
}

// float <-> order-preserving uint key (for atomic max pooling)
__device__ __forceinline__ unsigned fkey(float f) {
    unsigned b = __float_as_uint(f);
    return (b & 0x80000000u) ? ~b : (b | 0x80000000u);
}
__device__ __forceinline__ float fdec(unsigned k) {
    unsigned b = (k & 0x80000000u) ? (k ^ 0x80000000u) : ~k;
    return __uint_as_float(b);
}

// ================= kernel 1: XW1^T = (x @ W1)^T -> f16 ======================
// 256 CTAs x 64 nodes. W1 staged in smem; thread computes 4 nodes x 4 h.
__global__ void __launch_bounds__(256) k_xw1t(const float* __restrict__ x,
                                              const float* __restrict__ W1) {
    extern __shared__ __align__(16) float s_xw[];
    float* sW = s_xw;                 // [256][64]
    float* sx = s_xw + NFEAT * NH;    // [64][260] (pad 260 vs conflicts)
    const int tid = threadIdx.x;
    const int nodes0 = blockIdx.x * 64;

    if (blockIdx.x == 0 && tid < 2) g_maxkey[tid] = 0u;   // reset pooling keys

    #pragma unroll
    for (int i = 0; i < 16; i++)      // W1: 4096 float4
        ((float4*)sW)[tid + i * 256] = ((const float4*)W1)[tid + i * 256];
    #pragma unroll
    for (int i = 0; i < 16; i++) {    // x: 64 nodes x 64 float4
        int idx = tid + i * 256;
        int r = idx >> 6, c4 = idx & 63;
        float4 v = *(const float4*)(x + (size_t)(nodes0 + r) * NFEAT + c4 * 4);
        float* d = &sx[r * 260 + c4 * 4];
        d[0] = v.x; d[1] = v.y; d[2] = v.z; d[3] = v.w;
    }
    __syncthreads();

    const int hb = (tid & 15) * 4;     // 4 consecutive h
    const int n0 = (tid >> 4) * 4;     // 4 consecutive nodes
    float acc[4][4];
    #pragma unroll
    for (int j = 0; j < 4; j++)
        #pragma unroll
        for (int q = 0; q < 4; q++) acc[j][q] = 0.f;

    #pragma unroll 4
    for (int m = 0; m < NFEAT; m++) {
        float4 w = *(const float4*)&sW[m * NH + hb];
        #pragma unroll
        for (int j = 0; j < 4; j++) {
            float xv = sx[(n0 + j) * 260 + m];
            acc[j][0] = fmaf(xv, w.x, acc[j][0]);
            acc[j][1] = fmaf(xv, w.y, acc[j][1]);
            acc[j][2] = fmaf(xv, w.z, acc[j][2]);
            acc[j][3] = fmaf(xv, w.w, acc[j][3]);
        }
    }
    size_t nd = (size_t)nodes0 + n0;
    #pragma unroll
    for (int q = 0; q < 4; q++) {
        uint32_t p01 = pack_h2(acc[0][q], acc[1][q]);
        uint32_t p23 = pack_h2(acc[2][q], acc[3][q]);
        uint32_t* dst = (uint32_t*)(g_XW1T + (size_t)(hb + q) * NN + nd);
        dst[0] = p01; dst[1] = p23;
    }
}

// ================= kernel 2: T = relu(adj @ XW1 + b1) @ W2  (HMMA f16) ======
// 256 threads: warps 0-3 rows (wm*32..+31) K-half 0; warps 4-7 same rows K-half 1.
__device__ __forceinline__ void p1_load(const float* __restrict__ adj, size_t row0,
                                        int c, int tid, char* smem) {
    char* st = smem + (c % SSTAGE) * STAGE_B;
    const float* gA = adj + row0 * NN + (size_t)c * 32;
    const __half* gB = g_XW1T + (size_t)c * 32;
    #pragma unroll
    for (int i = 0; i < 4; i++) {                  // A: 128 rows x 8 x 16B
        int seg = tid + i * 256;
        int r = seg >> 3, c8 = seg & 7;
        cp_async16(st + r * 144 + c8 * 16, gA + (size_t)r * NN + c8 * 4);
    }
    {                                              // B: 64 rows x 4 x 16B (f16)
        int r = tid >> 2, c4 = tid & 3;
        cp_async16(st + A_STAGE + r * 80 + c4 * 16, gB + (size_t)r * NN + c4 * 8);
    }
}

__global__ void __launch_bounds__(256, 1)
k_pass1(const float* __restrict__ adj, const float* __restrict__ b1,
        const float* __restrict__ W2) {
    extern __shared__ __align__(16) char smem[];
    const int tid  = threadIdx.x;
    const int warp = tid >> 5, lane = tid & 31;
    const int g = lane >> 2, tig = lane & 3;
    const int wm = warp & 3;                 // row-group -> rows wm*32..+31
    const int ksF = (warp >> 2) * 16;        // K-half offset (elements)
    const size_t row0 = (size_t)blockIdx.x * 128;

    float acc[2][8][4];
    #pragma unroll
    for (int mt = 0; mt < 2; mt++)
        #pragma unroll
        for (int nt = 0; nt < 8; nt++)
            #pragma unroll
            for (int q = 0; q < 4; q++) acc[mt][nt][q] = 0.f;

    for (int s = 0; s < SSTAGE - 1; s++) { p1_load(adj, row0, s, tid, smem); CP_COMMIT(); }

    for (int c = 0; c < NCHUNK; c++) {
        CP_WAIT(SSTAGE - 2);
        __syncthreads();
        if (c + SSTAGE - 1 < NCHUNK) p1_load(adj, row0, c + SSTAGE - 1, tid, smem);
        CP_COMMIT();

        const float*  SA = (const float*)(smem + (c % SSTAGE) * STAGE_B);
        const __half* SB = (const __half*)(smem + (c % SSTAGE) * STAGE_B + A_STAGE);

        // B fragments: b0 = (k=2tig,2tig+1; n), b1 = (k+8; n)
        uint32_t bf[8][2];
        #pragma unroll
        for (int nt = 0; nt < 8; nt++) {
            const __half* br = SB + (nt * 8 + g) * BPITCHH + ksF + 2 * tig;
            bf[nt][0] = *(const uint32_t*)br;
            bf[nt][1] = *(const uint32_t*)(br + 8);
        }
        #pragma unroll
        for (int mt = 0; mt < 2; mt++) {
            const float* ar = SA + (wm * 32 + mt * 16 + g) * APITCHF + ksF + 2 * tig;
            float2 v0 = *(const float2*)ar;                     // row g,   k..k+1
            float2 v1 = *(const float2*)(ar + 8 * APITCHF);     // row g+8
            float2 v2 = *(const float2*)(ar + 8);               // row g,   k+8
            float2 v3 = *(const float2*)(ar + 8 * APITCHF + 8); // row g+8, k+8
            uint32_t a0 = pack_h2(v0.x * ADJ_SCALE, v0.y * ADJ_SCALE);
            uint32_t a1 = pack_h2(v1.x * ADJ_SCALE, v1.y * ADJ_SCALE);
            uint32_t a2 = pack_h2(v2.x * ADJ_SCALE, v2.y * ADJ_SCALE);
            uint32_t a3 = pack_h2(v3.x * ADJ_SCALE, v3.y * ADJ_SCALE);
            #pragma unroll
            for (int nt = 0; nt < 8; nt++)
                mma_f16(acc[mt][nt], a0, a1, a2, a3, bf[nt][0], bf[nt][1]);
        }
    }

    // ---- combine the two K-half partial accumulators via smem ----
    __syncthreads();
    float* xch = (float*)smem;               // reuse pipeline smem (loop done)
    if (warp >= 4) {
        float* dst = xch + ((warp - 4) * 32 + lane) * 68;
        #pragma unroll
        for (int mt = 0; mt < 2; mt++)
            #pragma unroll
            for (int nt = 0; nt < 8; nt++)
                #pragma unroll
                for (int q = 0; q < 4; q++)
                    dst[mt * 32 + nt * 4 + q] = acc[mt][nt][q];
    }
    __syncthreads();
    if (warp < 4) {
        const float* src = xch + (warp * 32 + lane) * 68;
        #pragma unroll
        for (int mt = 0; mt < 2; mt++)
            #pragma unroll
            for (int nt = 0; nt < 8; nt++)
                #pragma unroll
                for (int q = 0; q < 4; q++)
                    acc[mt][nt][q] += src[mt * 32 + nt * 4 + q];

        // epilogue: relu(acc/2^14 + b1) @ W2, quad reduce, write T
        float bb[8][2], w20[8][2], w21[8][2];
        #pragma unroll
        for (int nt = 0; nt < 8; nt++) {
            int j0 = nt * 8 + 2 * tig, j1 = j0 + 1;
            bb[nt][0]  = __ldg(b1 + j0);         bb[nt][1]  = __ldg(b1 + j1);
            w20[nt][0] = __ldg(W2 + 2 * j0);     w20[nt][1] = __ldg(W2 + 2 * j1);
            w21[nt][0] = __ldg(W2 + 2 * j0 + 1); w21[nt][1] = __ldg(W2 + 2 * j1 + 1);
        }
        #pragma unroll
        for (int mt = 0; mt < 2; mt++) {
            #pragma unroll
            for (int half = 0; half < 2; half++) {
                float t0 = 0.f, t1 = 0.f;
                #pragma unroll
                for (int nt = 0; nt < 8; nt++) {
                    float h0 = fmaxf(fmaf(acc[mt][nt][half * 2 + 0], ADJ_ISCALE, bb[nt][0]), 0.f);
                    float h1 = fmaxf(fmaf(acc[mt][nt][half * 2 + 1], ADJ_ISCALE, bb[nt][1]), 0.f);
                    t0 = fmaf(h0, w20[nt][0], fmaf(h1, w20[nt][1], t0));
                    t1 = fmaf(h0, w21[nt][0], fmaf(h1, w21[nt][1], t1));
                }
                t0 += __shfl_xor_sync(~0u, t0, 1); t1 += __shfl_xor_sync(~0u, t1, 1);
                t0 += __shfl_xor_sync(~0u, t0, 2); t1 += __shfl_xor_sync(~0u, t1, 2);
                if (tig == 0)
                    g_T[row0 + warp * 32 + mt * 16 + half * 8 + g] = make_float2(t0, t1);
            }
        }
    }
}

// ========== kernel 3: adj @ T + b2, fused column max + final linear =========
__global__ void __launch_bounds__(256) k_pass2(const float* __restrict__ adj,
                                               const float* __restrict__ b2,
                                               const float* __restrict__ W3,
                                               const float* __restrict__ b3,
                                               float* __restrict__ out) {
    __shared__ float sT0[4096];
    __shared__ float sT1[4096];
    __shared__ unsigned smax[8][2];
    const int tid = threadIdx.x, warp = tid >> 5, lane = tid & 31;
    const size_t row0 = (size_t)blockIdx.x * 32 + warp * 4;

    float a00 = 0, a01 = 0, a10 = 0, a11 = 0, a20 = 0, a21 = 0, a30 = 0, a31 = 0;

    for (int part = 0; part < 4; part++) {
        __syncthreads();
        for (int i = tid; i < 4096; i += 256) {
            float2 t = g_T[part * 4096 + i];
            sT0[i] = t.x; sT1[i] = t.y;
        }
        __syncthreads();
        const float* ap = adj + (size_t)part * 4096;
        #pragma unroll 2
        for (int j = lane * 4; j < 4096; j += 128) {
            float4 t0 = *(const float4*)&sT0[j];
            float4 t1 = *(const float4*)&sT1[j];
            float4 r0 = __ldcs((const float4*)(ap + (row0 + 0) * NN + j));
            float4 r1 = __ldcs((const float4*)(ap + (row0 + 1) * NN + j));
            float4 r2 = __ldcs((const float4*)(ap + (row0 + 2) * NN + j));
            float4 r3 = __ldcs((const float4*)(ap + (row0 + 3) * NN + j));
            a00 = fmaf(r0.x, t0.x, fmaf(r0.y, t0.y, fmaf(r0.z, t0.z, fmaf(r0.w, t0.w, a00))));
            a01 = fmaf(r0.x, t1.x, fmaf(r0.y, t1.y, fmaf(r0.z, t1.z, fmaf(r0.w, t1.w, a01))));
            a10 = fmaf(r1.x, t0.x, fmaf(r1.y, t0.y, fmaf(r1.z, t0.z, fmaf(r1.w, t0.w, a10))));
            a11 = fmaf(r1.x, t1.x, fmaf(r1.y, t1.y, fmaf(r1.z, t1.z, fmaf(r1.w, t1.w, a11))));
            a20 = fmaf(r2.x, t0.x, fmaf(r2.y, t0.y, fmaf(r2.z, t0.z, fmaf(r2.w, t0.w, a20))));
            a21 = fmaf(r2.x, t1.x, fmaf(r2.y, t1.y, fmaf(r2.z, t1.z, fmaf(r2.w, t1.w, a21))));
            a30 = fmaf(r3.x, t0.x, fmaf(r3.y, t0.y, fmaf(r3.z, t0.z, fmaf(r3.w, t0.w, a30))));
            a31 = fmaf(r3.x, t1.x, fmaf(r3.y, t1.y, fmaf(r3.z, t1.z, fmaf(r3.w, t1.w, a31))));
        }
    }
    #pragma unroll
    for (int off = 16; off; off >>= 1) {
        a00 += __shfl_xor_sync(~0u, a00, off); a01 += __shfl_xor_sync(~0u, a01, off);
        a10 += __shfl_xor_sync(~0u, a10, off); a11 += __shfl_xor_sync(~0u, a11, off);
        a20 += __shfl_xor_sync(~0u, a20, off); a21 += __shfl_xor_sync(~0u, a21, off);
        a30 += __shfl_xor_sync(~0u, a30, off); a31 += __shfl_xor_sync(~0u, a31, off);
    }
    if (lane == 0) {
        float bb0 = __ldg(b2), bb1 = __ldg(b2 + 1);
        unsigned k0 = fkey(a00 + bb0), k1 = fkey(a01 + bb1);
        k0 = max(k0, fkey(a10 + bb0)); k1 = max(k1, fkey(a11 + bb1));
        k0 = max(k0, fkey(a20 + bb0)); k1 = max(k1, fkey(a21 + bb1));
        k0 = max(k0, fkey(a30 + bb0)); k1 = max(k1, fkey(a31 + bb1));
        smax[warp][0] = k0; smax[warp][1] = k1;
    }
    __syncthreads();
    if (tid == 0) {
        unsigned k0 = smax[0][0], k1 = smax[0][1];
        #pragma unroll
        for (int w = 1; w < 8; w++) { k0 = max(k0, smax[w][0]); k1 = max(k1, smax[w][1]); }
        atomicMax(&g_maxkey[0], k0);
        atomicMax(&g_maxkey[1], k1);
        __threadfence();
        if (atomicAdd(&g_cnt, 1) == (int)gridDim.x - 1) {     // last CTA finishes
            float m0 = fdec(atomicMax(&g_maxkey[0], 0u));
            float m1 = fdec(atomicMax(&g_maxkey[1], 0u));
            out[0] = fmaf(m0, __ldg(W3), fmaf(m1, __ldg(W3 + 1), __ldg(b3)));
            g_cnt = 0;                                        // reset for next replay
        }
    }
}

// ================= launch ===================================================
extern "C" void kernel_launch(void* const* d_in, const int* in_sizes, int n_in,
                              void* d_out, int out_size) {
    (void)in_sizes; (void)n_in; (void)out_size;
    const float* x   = (const float*)d_in[0];
    const float* adj = (const float*)d_in[1];
    const float* W1  = (const float*)d_in[2];
    const float* b1  = (const float*)d_in[3];
    const float* W2  = (const float*)d_in[4];
    const float* b2  = (const float*)d_in[5];
    const float* W3  = (const float*)d_in[6];
    const float* b3  = (const float*)d_in[7];
    float* out = (float*)d_out;

    static int cfg_done = 0;
    if (!cfg_done) {
        cudaFuncSetAttribute(k_pass1, cudaFuncAttributeMaxDynamicSharedMemorySize, DYN);
        cudaFuncSetAttribute(k_xw1t, cudaFuncAttributeMaxDynamicSharedMemorySize, XW_DYN);
        cfg_done = 1;
    }

    k_xw1t <<<256, 256, XW_DYN>>>(x, W1);
    k_pass1<<<128, 256, DYN>>>(adj, b1, W2);
    k_pass2<<<512, 256>>>(adj, b2, W3, b3, out);
}